// round 15
// baseline (speedup 1.0000x reference)
#include <cuda_runtime.h>

#define B_ 4
#define N_ 128
#define L_ 20
#define D_ 512
#define KR (B_*L_)            // 80
#define SCALE 0.044194173824159216f   // 1/sqrt(512)

// ---- scratch (no allocation allowed) ----
__device__ float g_k[KR*D_];          // k  = f_w @ Wk^T + bk
__device__ float g_kk[KR*D_];         // kk = k @ Wq
__device__ float g_c[KR];             // c[l] = bq . k[l]
__device__ float g_fbq[B_*N_*D_];     // gated boundary features
__device__ float g_Ab[B_*N_*N_];      // boundary self-attention

// ============================================================
// Small-GEMM, no K-split: C[80,512] tile TM=8 x TN=32, 128 thr.
// ============================================================
template<bool TRANSB, bool BIAS, bool CEPI>
__global__ void __launch_bounds__(128)
gemm8(const float* __restrict__ A, const float* __restrict__ Bm,
      const float* __restrict__ bias, const float* __restrict__ bqv,
      float* __restrict__ C, float* __restrict__ cvec)
{
    const int Kd = D_, Nd = D_;
    int row0 = blockIdx.x * 8;     // gridx = 10
    int col0 = blockIdx.y * 32;    // gridy = 16

    __shared__ float As[8][33];
    __shared__ float Bs[32][36];

    int t = threadIdx.x;
    int c  = t & 31;
    int rh = t >> 5;               // 0..3 -> rows rh*2, rh*2+1

    float acc0 = 0.f, acc1 = 0.f;

    for (int k0 = 0; k0 < Kd; k0 += 32) {
        {
            int kc = t & 31, r2 = (t >> 5) * 2;
            As[r2][kc]     = A[(row0 + r2) * Kd + k0 + kc];
            As[r2 + 1][kc] = A[(row0 + r2 + 1) * Kd + k0 + kc];
        }
        if (TRANSB) {
            int cc = t >> 2, h = t & 3;
            const float4* bp = (const float4*)(Bm + (long)(col0 + cc) * Kd + k0 + h * 8);
            #pragma unroll
            for (int q = 0; q < 2; q++) {
                float4 v = bp[q];
                int kc = h * 8 + q * 4;
                Bs[kc][cc] = v.x; Bs[kc+1][cc] = v.y; Bs[kc+2][cc] = v.z; Bs[kc+3][cc] = v.w;
            }
        } else {
            #pragma unroll
            for (int p = 0; p < 2; p++) {
                int kc = (t >> 3) + p * 16;
                int c4 = (t & 7) * 4;
                float4 v = *(const float4*)(Bm + (long)(k0 + kc) * Nd + col0 + c4);
                Bs[kc][c4] = v.x; Bs[kc][c4+1] = v.y; Bs[kc][c4+2] = v.z; Bs[kc][c4+3] = v.w;
            }
        }
        __syncthreads();
        #pragma unroll
        for (int kc = 0; kc < 32; kc++) {
            float bv = Bs[kc][c];
            acc0 = fmaf(As[rh*2][kc],     bv, acc0);
            acc1 = fmaf(As[rh*2 + 1][kc], bv, acc1);
        }
        __syncthreads();
    }
    float bb = BIAS ? bias[col0 + c] : 0.f;
    C[(row0 + rh*2)     * Nd + col0 + c] = acc0 + bb;
    C[(row0 + rh*2 + 1) * Nd + col0 + c] = acc1 + bb;

    if (CEPI && blockIdx.y == 0) {
        __shared__ float cred[8][17];
        int r = t >> 4, seg = t & 15;
        float s = 0.f;
        const float4* kr  = (const float4*)(A + (long)(row0 + r) * Kd + seg * 32);
        const float4* bq4 = (const float4*)(bqv + seg * 32);
        #pragma unroll
        for (int q = 0; q < 8; q++) {
            float4 kv = kr[q], bv = bq4[q];
            s += kv.x*bv.x + kv.y*bv.y + kv.z*bv.z + kv.w*bv.w;
        }
        cred[r][seg] = s;
        __syncthreads();
        if (t < 8) {
            float tot = 0.f;
            #pragma unroll
            for (int q = 0; q < 16; q++) tot += cred[t][q];
            cvec[row0 + t] = tot;
        }
    }
}

// cross-attention (L=20) + sentence gating -> f_bq ; also out = f_b (init)
__global__ void __launch_bounds__(256) attn_kernel(const float* __restrict__ f_b,
                                                   const float* __restrict__ f_w,
                                                   const float* __restrict__ f_s,
                                                   float* __restrict__ out)
{
    int bn = blockIdx.x; int b = bn >> 7;
    __shared__ float fb[D_];
    __shared__ float sl[L_];
    int tid = threadIdx.x;
    fb[tid]       = f_b[bn*D_ + tid];
    fb[tid + 256] = f_b[bn*D_ + tid + 256];
    __syncthreads();
    int w = tid >> 5, lane = tid & 31;
    for (int l = w; l < L_; l += 8) {
        const float* kr = g_kk + (b*L_ + l) * D_;
        float p = 0.f;
        #pragma unroll
        for (int e = lane; e < D_; e += 32) p = fmaf(fb[e], kr[e], p);
        #pragma unroll
        for (int off = 16; off > 0; off >>= 1) p += __shfl_xor_sync(0xffffffffu, p, off);
        if (lane == 0) sl[l] = (p + g_c[b*L_ + l]) * SCALE;
    }
    __syncthreads();
    if (tid == 0) {
        float mx = sl[0];
        #pragma unroll
        for (int l = 1; l < L_; l++) mx = fmaxf(mx, sl[l]);
        float s = 0.f;
        #pragma unroll
        for (int l = 0; l < L_; l++) { float e = __expf(sl[l] - mx); sl[l] = e; s += e; }
        float inv = __fdividef(1.f, s);
        #pragma unroll
        for (int l = 0; l < L_; l++) sl[l] *= inv;
    }
    __syncthreads();
    for (int d = tid; d < D_; d += 256) {
        float acc = 0.f;
        #pragma unroll
        for (int l = 0; l < L_; l++) acc += sl[l] * f_w[(b*L_ + l)*D_ + d];
        g_fbq[bn*D_ + d] = fb[d] * (acc + f_s[b*D_ + d]);
        out[bn*D_ + d] = fb[d];          // init residual for final RED.ADD
    }
}

// ============================================================
// score_fused: score GEMM + in-warp softmax, NO partials.
// Tile 8 rows x 128 cols, 128 threads, 2x4 micro-tile, full K.
// Each score row lives in ONE warp -> softmax = warp shuffles.
// grid (16 row-tiles, 4 batches) = 64 blocks.
// ============================================================
__global__ void __launch_bounds__(128) score_fused()
{
    int b = blockIdx.y;
    int row0 = blockIdx.x * 8;
    const float* Ab_ = g_fbq + (long)b * N_ * D_;

    __shared__ float As[16][9];       // [kc][row]
    __shared__ float Bs[16][132];     // [kc][col]

    int t  = threadIdx.x;
    int tc = t & 31;                  // 4-col group
    int tr = t >> 5;                  // warp id -> rows tr*2, tr*2+1

    float acc[2][4];
    #pragma unroll
    for (int i = 0; i < 2; i++)
        #pragma unroll
        for (int j = 0; j < 4; j++) acc[i][j] = 0.f;

    for (int k0 = 0; k0 < D_; k0 += 16) {
        // As: 8 rows x 16 kc = 128 elems, 1/thread
        {
            int r = t >> 4, kc = t & 15;
            As[kc][r] = Ab_[(long)(row0 + r) * D_ + k0 + kc];
        }
        // Bs: 16 kc x 128 cols; thread t owns col t, one float4x4 = 16 kc
        {
            const float4* bp = (const float4*)(Ab_ + (long)t * D_ + k0);
            #pragma unroll
            for (int q = 0; q < 4; q++) {
                float4 v = bp[q];
                int kc = q * 4;
                Bs[kc][t] = v.x; Bs[kc+1][t] = v.y; Bs[kc+2][t] = v.z; Bs[kc+3][t] = v.w;
            }
        }
        __syncthreads();
        #pragma unroll
        for (int kc = 0; kc < 16; kc++) {
            float a0 = As[kc][tr*2];
            float a1 = As[kc][tr*2 + 1];
            float4 bv = *(const float4*)&Bs[kc][tc * 4];
            acc[0][0] = fmaf(a0, bv.x, acc[0][0]); acc[0][1] = fmaf(a0, bv.y, acc[0][1]);
            acc[0][2] = fmaf(a0, bv.z, acc[0][2]); acc[0][3] = fmaf(a0, bv.w, acc[0][3]);
            acc[1][0] = fmaf(a1, bv.x, acc[1][0]); acc[1][1] = fmaf(a1, bv.y, acc[1][1]);
            acc[1][2] = fmaf(a1, bv.z, acc[1][2]); acc[1][3] = fmaf(a1, bv.w, acc[1][3]);
        }
        __syncthreads();
    }

    // in-warp softmax: warp tr owns rows tr*2, tr*2+1 (lane = 4 cols each)
    #pragma unroll
    for (int i = 0; i < 2; i++) {
        int row = row0 + tr * 2 + i;
        float v0 = acc[i][0] * SCALE, v1 = acc[i][1] * SCALE;
        float v2 = acc[i][2] * SCALE, v3 = acc[i][3] * SCALE;
        float mx = fmaxf(fmaxf(v0, v1), fmaxf(v2, v3));
        #pragma unroll
        for (int off = 16; off > 0; off >>= 1) mx = fmaxf(mx, __shfl_xor_sync(0xffffffffu, mx, off));
        float e0 = __expf(v0 - mx), e1 = __expf(v1 - mx);
        float e2 = __expf(v2 - mx), e3 = __expf(v3 - mx);
        float s = e0 + e1 + e2 + e3;
        #pragma unroll
        for (int off = 16; off > 0; off >>= 1) s += __shfl_xor_sync(0xffffffffu, s, off);
        float inv = __fdividef(1.f, s);
        *(float4*)&g_Ab[((long)b*N_ + row) * N_ + tc * 4] =
            make_float4(e0*inv, e1*inv, e2*inv, e3*inv);
    }
}

// sigmoid(x) = 0.5*tanh(0.5x)+0.5 — 1 MUFU instead of 2
__device__ __forceinline__ float sigmoid_fast(float x)
{
    float t;
    asm("tanh.approx.f32 %0, %1;" : "=f"(t) : "f"(0.5f * x));
    return fmaf(0.5f, t, 0.5f);
}

// ============================================================
// final_split: f_m stream, m-split x4, float4 loads.
// thread = (jj = t>>7, d4 = t&127); RED.ADD into out (pre-inited to f_b).
// ============================================================
__global__ void __launch_bounds__(512)
final_split(const float* __restrict__ f_b, const float* __restrict__ f_s,
            const float* __restrict__ f_m, float* __restrict__ out)
{
    int bidx  = blockIdx.x;          // 0..511
    int split = bidx & 3;
    int jg    = (bidx >> 2) & 31;
    int b     = bidx >> 7;
    int j0    = jg * 4;
    int m0    = split * 32;
    int t     = threadIdx.x;
    int jj    = t >> 7;              // 0..3
    int d4    = t & 127;             // float4 index over D

    __shared__ float2 a2[4][32];     // {A_b[b][j][m], A_b[b][m][j]}
    if (t < 128) {
        int j2 = t >> 5, m = t & 31;
        a2[j2][m] = make_float2(g_Ab[(b*N_ + j0 + j2)*N_ + m0 + m],
                                g_Ab[(b*N_ + m0 + m)*N_ + j0 + j2]);
    }
    __syncthreads();

    float4 fsd = ((const float4*)(f_s + (long)b * D_))[d4];
    float4 acc = make_float4(0.f, 0.f, 0.f, 0.f);

    #pragma unroll 8
    for (int m = 0; m < 32; m++) {
        float4 x   = ((const float4*)(f_m + ((((long)(b*N_ + m0 + m))*N_) + j0 + jj) * D_))[d4];
        float4 fbv = ((const float4*)(f_b + ((long)(b*N_ + m0 + m)) * D_))[d4];
        float2 a = a2[jj][m];
        float sgx = sigmoid_fast(x.x * fsd.x);
        float sgy = sigmoid_fast(x.y * fsd.y);
        float sgz = sigmoid_fast(x.z * fsd.z);
        float sgw = sigmoid_fast(x.w * fsd.w);
        acc.x = fmaf(a.x, fbv.x, acc.x); acc.x = fmaf(a.y * sgx, x.x, acc.x);
        acc.y = fmaf(a.x, fbv.y, acc.y); acc.y = fmaf(a.y * sgy, x.y, acc.y);
        acc.z = fmaf(a.x, fbv.z, acc.z); acc.z = fmaf(a.y * sgz, x.z, acc.z);
        acc.w = fmaf(a.x, fbv.w, acc.w); acc.w = fmaf(a.y * sgw, x.w, acc.w);
    }
    float* o = out + ((long)(b*N_ + j0 + jj)) * D_ + d4 * 4;
    atomicAdd(o + 0, acc.x);
    atomicAdd(o + 1, acc.y);
    atomicAdd(o + 2, acc.z);
    atomicAdd(o + 3, acc.w);
}

extern "C" void kernel_launch(void* const* d_in, const int* in_sizes, int n_in,
                              void* d_out, int out_size)
{
    const float* f_b = (const float*)d_in[0];
    const float* f_w = (const float*)d_in[1];
    const float* f_s = (const float*)d_in[2];
    const float* f_m = (const float*)d_in[3];
    const float* Wq  = (const float*)d_in[4];
    const float* bq  = (const float*)d_in[5];
    const float* Wk  = (const float*)d_in[6];
    const float* bk  = (const float*)d_in[7];
    float* out = (float*)d_out;

    void *p_k, *p_kk, *p_c;
    cudaGetSymbolAddress(&p_k,  g_k);
    cudaGetSymbolAddress(&p_kk, g_kk);
    cudaGetSymbolAddress(&p_c,  g_c);

    // 1) k = f_w @ Wk^T + bk            (TRANSB, bias)
    gemm8<true, true, false><<<dim3(10, 16), 128>>>(f_w, Wk, bk, nullptr,
                                                    (float*)p_k, nullptr);
    // 2) kk = k @ Wq ; c = bq . k       (NN, c-epilogue)
    gemm8<false, false, true><<<dim3(10, 16), 128>>>((const float*)p_k, Wq, nullptr, bq,
                                                     (float*)p_kk, (float*)p_c);
    // 3) cross-attn softmax + gating -> f_bq ; out = f_b
    attn_kernel<<<B_*N_, 256>>>(f_b, f_w, f_s, out);
    // 4) fused score GEMM + in-warp softmax -> A_b (no partials, no extra node)
    score_fused<<<dim3(16, B_), 128>>>();
    // 5) f_m stream (float4), m-split x4, RED.ADD into out
    final_split<<<512, 512>>>(f_b, f_s, f_m, out);
}

// round 16
// speedup vs baseline: 1.4575x; 1.4575x over previous
#include <cuda_runtime.h>

#define B_ 4
#define N_ 128
#define L_ 20
#define D_ 512
#define KR (B_*L_)            // 80
#define NSPLIT 8              // score GEMM K-split
#define SCALE 0.044194173824159216f   // 1/sqrt(512)

// ---- scratch (no allocation allowed) ----
__device__ float g_k[KR*D_];               // k = f_w @ Wk^T + bk
__device__ float g_kk[KR*D_];              // kk = k @ Wq
__device__ float g_c[KR];                  // c  = bq . k
__device__ float g_fbq[B_*N_*D_];          // gated boundary features
__device__ float g_Ab[B_*N_*N_];           // boundary self-attention
__device__ float g_part[B_*NSPLIT*N_*N_];  // K-split partials (proj: 4*80*512 fits)
__device__ float g_fp[4*B_*N_*D_];         // m-split partials of the final kernel

// ============================================================
// Generic fp32 K-split partial GEMM (R2-proven).
// TRANSB:  C[r][c] = sum_k A[r][k]*B[c][k]
// !TRANSB: C[r][c] = sum_k A[r][k]*B[k][c]
// Tile 16x128, 128 threads, 4x4 micro-tile, KC=16.
// ============================================================
template<bool TRANSB>
__global__ void __launch_bounds__(128)
gemm_part(const float* __restrict__ A, const float* __restrict__ B,
          float* __restrict__ Cpart, int M, int Ncol, int K, int ldB,
          int nsplit, int strideA, int strideB)
{
    const int TM = 16, TN = 128, KC = 16;
    int batch = blockIdx.z / nsplit;
    int split = blockIdx.z - batch * nsplit;
    int klen  = K / nsplit;
    int kbase = split * klen;
    A += (long)batch * strideA;
    B += (long)batch * strideB;
    float* C = Cpart + (long)(batch * nsplit + split) * M * Ncol;

    __shared__ float As[KC][TM];
    __shared__ float Bs[KC][TN];

    int row0 = blockIdx.x * TM;
    int col0 = blockIdx.y * TN;
    int tid = threadIdx.x;
    int tr = tid >> 5;      // 0..3
    int tc = tid & 31;      // 0..31

    float acc[4][4];
    #pragma unroll
    for (int i = 0; i < 4; i++)
        #pragma unroll
        for (int j = 0; j < 4; j++) acc[i][j] = 0.f;

    for (int kb = 0; kb < klen; kb += KC) {
        int k0 = kbase + kb;
        {
            int idx = tid * 2;
            int r = idx >> 4, kc = idx & 15;
            float2 av = *(const float2*)(A + (long)(row0 + r) * K + k0 + kc);
            As[kc][r]     = av.x;
            As[kc + 1][r] = av.y;
        }
        if (TRANSB) {
            const float* bp = B + (long)(col0 + tid) * ldB + k0;
            #pragma unroll
            for (int q = 0; q < 4; q++) {
                float4 v = *(const float4*)(bp + q * 4);
                Bs[q*4+0][tid] = v.x; Bs[q*4+1][tid] = v.y;
                Bs[q*4+2][tid] = v.z; Bs[q*4+3][tid] = v.w;
            }
        } else {
            #pragma unroll
            for (int p = 0; p < 4; p++) {
                int kc = (tid >> 5) + p * 4;
                int c4 = (tid & 31) * 4;
                float4 v = *(const float4*)(B + (long)(k0 + kc) * ldB + col0 + c4);
                *(float4*)&Bs[kc][c4] = v;
            }
        }
        __syncthreads();
        #pragma unroll
        for (int kc = 0; kc < KC; kc++) {
            float4 a4 = ((const float4*)As[kc])[tr];
            float4 b4 = ((const float4*)Bs[kc])[tc];
            acc[0][0] += a4.x*b4.x; acc[0][1] += a4.x*b4.y; acc[0][2] += a4.x*b4.z; acc[0][3] += a4.x*b4.w;
            acc[1][0] += a4.y*b4.x; acc[1][1] += a4.y*b4.y; acc[1][2] += a4.y*b4.z; acc[1][3] += a4.y*b4.w;
            acc[2][0] += a4.z*b4.x; acc[2][1] += a4.z*b4.y; acc[2][2] += a4.z*b4.z; acc[2][3] += a4.z*b4.w;
            acc[3][0] += a4.w*b4.x; acc[3][1] += a4.w*b4.y; acc[3][2] += a4.w*b4.z; acc[3][3] += a4.w*b4.w;
        }
        __syncthreads();
    }
    #pragma unroll
    for (int i = 0; i < 4; i++) {
        int row = row0 + tr * 4 + i;
        float4 v = make_float4(acc[i][0], acc[i][1], acc[i][2], acc[i][3]);
        *(float4*)(C + (long)row * Ncol + col0 + tc * 4) = v;
    }
}

// k = sum(partials) + bk ; c[r] = bq . k[r]
__global__ void __launch_bounds__(512) reduce_k_bias(const float* __restrict__ bk,
                                                     const float* __restrict__ bq)
{
    int r = blockIdx.x, d = threadIdx.x;
    float v = g_part[r*D_ + d] + g_part[(KR + r)*D_ + d]
            + g_part[(2*KR + r)*D_ + d] + g_part[(3*KR + r)*D_ + d] + bk[d];
    g_k[r*D_ + d] = v;
    float p = v * bq[d];
    #pragma unroll
    for (int off = 16; off > 0; off >>= 1) p += __shfl_xor_sync(0xffffffffu, p, off);
    __shared__ float red[16];
    if ((d & 31) == 0) red[d >> 5] = p;
    __syncthreads();
    if (d < 32) {
        float s = (d < 16) ? red[d] : 0.f;
        #pragma unroll
        for (int off = 8; off > 0; off >>= 1) s += __shfl_xor_sync(0xffffffffu, s, off);
        if (d == 0) g_c[r] = s;
    }
}

__global__ void __launch_bounds__(256) reduce_kk()
{
    int i = blockIdx.x * 256 + threadIdx.x;   // over KR*D_/4 = 10240 float4
    const float4* p = (const float4*)g_part;
    float4 a = p[i], b = p[10240 + i], c = p[2*10240 + i], e = p[3*10240 + i];
    ((float4*)g_kk)[i] = make_float4(a.x+b.x+c.x+e.x, a.y+b.y+c.y+e.y,
                                     a.z+b.z+c.z+e.z, a.w+b.w+c.w+e.w);
}

// cross-attention (L=20) + sentence gating -> f_bq
__global__ void __launch_bounds__(256) attn_kernel(const float* __restrict__ f_b,
                                                   const float* __restrict__ f_w,
                                                   const float* __restrict__ f_s)
{
    int bn = blockIdx.x; int b = bn >> 7;
    __shared__ float fb[D_];
    __shared__ float sl[L_];
    int tid = threadIdx.x;
    fb[tid]       = f_b[bn*D_ + tid];
    fb[tid + 256] = f_b[bn*D_ + tid + 256];
    __syncthreads();
    int w = tid >> 5, lane = tid & 31;
    for (int l = w; l < L_; l += 8) {
        const float* kr = g_kk + (b*L_ + l) * D_;
        float p = 0.f;
        #pragma unroll
        for (int e = lane; e < D_; e += 32) p = fmaf(fb[e], kr[e], p);
        #pragma unroll
        for (int off = 16; off > 0; off >>= 1) p += __shfl_xor_sync(0xffffffffu, p, off);
        if (lane == 0) sl[l] = (p + g_c[b*L_ + l]) * SCALE;
    }
    __syncthreads();
    if (tid == 0) {
        float mx = sl[0];
        #pragma unroll
        for (int l = 1; l < L_; l++) mx = fmaxf(mx, sl[l]);
        float s = 0.f;
        #pragma unroll
        for (int l = 0; l < L_; l++) { float e = __expf(sl[l] - mx); sl[l] = e; s += e; }
        float inv = __fdividef(1.f, s);
        #pragma unroll
        for (int l = 0; l < L_; l++) sl[l] *= inv;
    }
    __syncthreads();
    for (int d = tid; d < D_; d += 256) {
        float acc = 0.f;
        #pragma unroll
        for (int l = 0; l < L_; l++) acc += sl[l] * f_w[(b*L_ + l)*D_ + d];
        g_fbq[bn*D_ + d] = fb[d] * (acc + f_s[b*D_ + d]);
    }
}

// sum NSPLIT score partials, scale, row softmax -> A_b
__global__ void __launch_bounds__(128) score_softmax()
{
    int bn = blockIdx.x; int b = bn >> 7; int n = bn & 127;
    int m = threadIdx.x;
    float s = 0.f;
    #pragma unroll
    for (int sp = 0; sp < NSPLIT; sp++) s += g_part[(((b*NSPLIT + sp)*N_) + n)*N_ + m];
    s *= SCALE;
    __shared__ float red[4];
    float mx = s;
    #pragma unroll
    for (int off = 16; off > 0; off >>= 1) mx = fmaxf(mx, __shfl_xor_sync(0xffffffffu, mx, off));
    if ((m & 31) == 0) red[m >> 5] = mx;
    __syncthreads();
    mx = fmaxf(fmaxf(red[0], red[1]), fmaxf(red[2], red[3]));
    float e = __expf(s - mx);
    __syncthreads();
    float sm = e;
    #pragma unroll
    for (int off = 16; off > 0; off >>= 1) sm += __shfl_xor_sync(0xffffffffu, sm, off);
    if ((m & 31) == 0) red[m >> 5] = sm;
    __syncthreads();
    sm = red[0] + red[1] + red[2] + red[3];
    g_Ab[bn*N_ + m] = e * __fdividef(1.f, sm);
}

// sigmoid(x) = 0.5*tanh(0.5x)+0.5 — 1 MUFU instead of 2
__device__ __forceinline__ float sigmoid_fast(float x)
{
    float t;
    asm("tanh.approx.f32 %0, %1;" : "=f"(t) : "f"(0.5f * x));
    return fmaf(0.5f, t, 0.5f);
}

// ============================================================
// final_split: f_m stream, m-split x4, float4 loads, NO atomics.
// thread = (jj = t>>7, d4 = t&127). Writes float4 partial to g_fp.
// ============================================================
__global__ void __launch_bounds__(512)
final_split(const float* __restrict__ f_b, const float* __restrict__ f_s,
            const float* __restrict__ f_m)
{
    int bidx  = blockIdx.x;          // 0..511
    int split = bidx & 3;
    int jg    = (bidx >> 2) & 31;
    int b     = bidx >> 7;
    int j0    = jg * 4;
    int m0    = split * 32;
    int t     = threadIdx.x;
    int jj    = t >> 7;              // 0..3
    int d4    = t & 127;             // float4 index over D

    __shared__ float2 a2[4][32];     // {A_b[b][j][m], A_b[b][m][j]}
    if (t < 128) {
        int j2 = t >> 5, m = t & 31;
        a2[j2][m] = make_float2(g_Ab[(b*N_ + j0 + j2)*N_ + m0 + m],
                                g_Ab[(b*N_ + m0 + m)*N_ + j0 + j2]);
    }
    __syncthreads();

    float4 fsd = ((const float4*)(f_s + (long)b * D_))[d4];
    float4 acc = make_float4(0.f, 0.f, 0.f, 0.f);

    #pragma unroll 8
    for (int m = 0; m < 32; m++) {
        float4 x   = ((const float4*)(f_m + ((((long)(b*N_ + m0 + m))*N_) + j0 + jj) * D_))[d4];
        float4 fbv = ((const float4*)(f_b + ((long)(b*N_ + m0 + m)) * D_))[d4];
        float2 a = a2[jj][m];
        float sgx = sigmoid_fast(x.x * fsd.x);
        float sgy = sigmoid_fast(x.y * fsd.y);
        float sgz = sigmoid_fast(x.z * fsd.z);
        float sgw = sigmoid_fast(x.w * fsd.w);
        acc.x = fmaf(a.x, fbv.x, acc.x); acc.x = fmaf(a.y * sgx, x.x, acc.x);
        acc.y = fmaf(a.x, fbv.y, acc.y); acc.y = fmaf(a.y * sgy, x.y, acc.y);
        acc.z = fmaf(a.x, fbv.z, acc.z); acc.z = fmaf(a.y * sgz, x.z, acc.z);
        acc.w = fmaf(a.x, fbv.w, acc.w); acc.w = fmaf(a.y * sgw, x.w, acc.w);
    }
    ((float4*)(g_fp + ((long)((split*B_ + b)*N_ + j0 + jj)) * D_))[d4] = acc;
}

// out = f_b + sum of 4 m-split partials (float4, 64K vectors)
__global__ void __launch_bounds__(512) reduce_final(const float* __restrict__ f_b,
                                                    float* __restrict__ out)
{
    int i = blockIdx.x * 512 + threadIdx.x;   // over B*N*D/4 = 65536 float4
    const int S = B_*N_*D_/4;                  // 65536
    const float4* p = (const float4*)g_fp;
    float4 r = ((const float4*)f_b)[i];
    float4 a = p[i], bb = p[S + i], c = p[2*S + i], e = p[3*S + i];
    r.x += a.x + bb.x + c.x + e.x;
    r.y += a.y + bb.y + c.y + e.y;
    r.z += a.z + bb.z + c.z + e.z;
    r.w += a.w + bb.w + c.w + e.w;
    ((float4*)out)[i] = r;
}

extern "C" void kernel_launch(void* const* d_in, const int* in_sizes, int n_in,
                              void* d_out, int out_size)
{
    const float* f_b = (const float*)d_in[0];
    const float* f_w = (const float*)d_in[1];
    const float* f_s = (const float*)d_in[2];
    const float* f_m = (const float*)d_in[3];
    const float* Wq  = (const float*)d_in[4];
    const float* bq  = (const float*)d_in[5];
    const float* Wk  = (const float*)d_in[6];
    const float* bk  = (const float*)d_in[7];
    float* out = (float*)d_out;

    void *p_part, *p_k, *p_fbq;
    cudaGetSymbolAddress(&p_part, g_part);
    cudaGetSymbolAddress(&p_k,    g_k);
    cudaGetSymbolAddress(&p_fbq,  g_fbq);

    // 1) k partials: f_w[80,512] @ Wk^T        (NT, K-split 4)
    gemm_part<true><<<dim3(5, 4, 4), 128>>>(f_w, Wk, (float*)p_part,
                                            KR, D_, D_, D_, 4, 0, 0);
    // 2) k = sum + bk ; c = bq . k
    reduce_k_bias<<<KR, 512>>>(bk, bq);
    // 3) kk partials: k @ Wq                   (NN, K-split 4)
    gemm_part<false><<<dim3(5, 4, 4), 128>>>((const float*)p_k, Wq, (float*)p_part,
                                             KR, D_, D_, D_, 4, 0, 0);
    reduce_kk<<<40, 256>>>();
    // 4) cross-attn softmax + gating -> f_bq
    attn_kernel<<<B_*N_, 256>>>(f_b, f_w, f_s);
    // 5) self-attn score partials per batch    (NT, batched, K-split 8 -> 256 blocks)
    gemm_part<true><<<dim3(8, 1, B_*NSPLIT), 128>>>((const float*)p_fbq, (const float*)p_fbq,
                                                    (float*)p_part, N_, N_, D_, D_, NSPLIT,
                                                    N_*D_, N_*D_);
    score_softmax<<<B_*N_, 128>>>();
    // 6) DRAM-bound f_m stream, m-split x4, float4, partials (no atomics)
    final_split<<<512, 512>>>(f_b, f_s, f_m);
    reduce_final<<<128, 512>>>(f_b, out);
}